// round 13
// baseline (speedup 1.0000x reference)
#include <cuda_runtime.h>
#include <cuda_fp16.h>
#include <cstdint>

#define BATCH 16384
#define DMODEL 1024
#define ODIM 572
#define ODIM_PAD 576

#define BM 128
#define BN 64
#define BK 32
#define KT (DMODEL / BK)
#define NB (ODIM_PAD / BN)   // 9 n-blocks
#define NMB (BATCH / BM)     // 128 m-blocks
#define SSTRIDE 40  // 32 + 8 pad: 80B rows -> conflict-free ldmatrix, 16B-aligned

// ---------------- scratch (device globals; no allocation) ----------------
__device__ __half g_Ah[BATCH * DMODEL];              // A rounded once to fp16
__device__ __half g_WhT[ODIM_PAD * DMODEL];          // [n][k] transposed, padded, fp16
__device__ float g_pre[BATCH * ODIM];
__device__ unsigned int g_cnt[NMB];                  // arrival counters (self-resetting)

// ---------------- Threefry-2x32, key = PRNGKey(42) = (0, 42) ----------------
__device__ __forceinline__ uint32_t rotl32(uint32_t v, int d) {
    return __funnelshift_l(v, v, d);
}

__device__ __forceinline__ void threefry_0_42(uint32_t c0, uint32_t c1,
                                              uint32_t& o0, uint32_t& o1) {
    const uint32_t K0 = 0u, K1 = 42u, K2 = 0u ^ 42u ^ 0x1BD11BDAu;
    uint32_t x0 = c0 + K0;
    uint32_t x1 = c1 + K1;
#define RND(r) { x0 += x1; x1 = rotl32(x1, r) ^ x0; }
    RND(13) RND(15) RND(26) RND(6)
    x0 += K1; x1 += K2 + 1u;
    RND(17) RND(29) RND(16) RND(24)
    x0 += K2; x1 += K0 + 2u;
    RND(13) RND(15) RND(26) RND(6)
    x0 += K0; x1 += K1 + 3u;
    RND(17) RND(29) RND(16) RND(24)
    x0 += K1; x1 += K2 + 4u;
    RND(13) RND(15) RND(26) RND(6)
    x0 += K2; x1 += K0 + 5u;
#undef RND
    o0 = x0; o1 = x1;
}

// JAX threefry_partitionable random_bits, bit_width=32:
//   counter words (0, elem); 32-bit output = bits1 ^ bits2
__device__ __forceinline__ float gumbel_at(uint32_t elem) {
    uint32_t o0, o1;
    threefry_0_42(0u, elem, o0, o1);
    uint32_t bits = o0 ^ o1;
    const float TINY = 1.17549435e-38f;
    float f = __uint_as_float((bits >> 9) | 0x3F800000u) - 1.0f;  // [0,1)
    float u = fmaxf(TINY, f + TINY);
    return -__logf(-__logf(u));
}

// ---------------- convert A: fp32 -> fp16 (vectorized) ----------------
__global__ void convert_a_kernel(const float* __restrict__ A) {
    int stride = gridDim.x * blockDim.x;
    const float2* A2 = (const float2*)A;
    __half2* out2 = (__half2*)g_Ah;
    for (int i = blockIdx.x * blockDim.x + threadIdx.x; i < BATCH * DMODEL / 2; i += stride) {
        float2 a = A2[i];
        out2[i] = __floats2half2_rn(a.x, a.y);
    }
}

// ---------------- convert W1: transpose + pad + fp16 ----------------
__global__ void convert_w_kernel(const float* __restrict__ W1) {
    int stride = gridDim.x * blockDim.x;
    for (int i = blockIdx.x * blockDim.x + threadIdx.x; i < ODIM_PAD * DMODEL; i += stride) {
        int n = i >> 10;          // DMODEL = 1024
        int k = i & 1023;
        float w = (n < ODIM) ? __ldg(&W1[k * ODIM + n]) : 0.0f;
        g_WhT[i] = __float2half(w);   // i == n*1024 + k
    }
}

// ---------------- GEMM + last-arriver finisher ----------------
#define MMA_F16(C, A, B)                                                      \
    asm volatile(                                                             \
        "mma.sync.aligned.m16n8k16.row.col.f32.f16.f16.f32 "                  \
        "{%0,%1,%2,%3}, {%4,%5,%6,%7}, {%8,%9}, {%0,%1,%2,%3};"               \
        : "+f"(C[0]), "+f"(C[1]), "+f"(C[2]), "+f"(C[3])                      \
        : "r"((A)[0]), "r"((A)[1]), "r"((A)[2]), "r"((A)[3]),                 \
          "r"((B)[0]), "r"((B)[1]))

#define LDSM4(R, addr)                                                        \
    asm volatile("ldmatrix.sync.aligned.m8n8.x4.shared.b16 {%0,%1,%2,%3}, [%4];" \
        : "=r"((R)[0]), "=r"((R)[1]), "=r"((R)[2]), "=r"((R)[3]) : "r"(addr))

__global__ __launch_bounds__(256) void gemm_kernel(
    const float* __restrict__ b1, const float* __restrict__ core,
    const float* __restrict__ W2, const float* __restrict__ b2,
    float* __restrict__ out) {
    __shared__ __align__(16) __half sA[2][BM][SSTRIDE];     // 20480 B
    __shared__ __align__(16) __half sW[2][BN][SSTRIDE];     // 10240 B
    __shared__ unsigned s_last;

    const int m_blk = blockIdx.y * BM;
    const int n_blk = blockIdx.x * BN;

    const int lane = threadIdx.x & 31;
    const int warp = threadIdx.x >> 5;     // 0..7
    const int wm = (warp & 3) * 32;        // 4 warps along M
    const int wn = (warp >> 2) * 32;       // 2 warps along N
    const int g = lane >> 2;   // 0..7
    const int tq = lane & 3;   // 0..3

    const int aRow = lane & 15;
    const int aCol = (lane & 16) >> 1;
    const int bRow = (lane & 7) + ((lane & 16) >> 1);
    const int bCol = lane & 8;

    float acc[2][4][4];
#pragma unroll
    for (int a = 0; a < 2; a++)
#pragma unroll
        for (int b = 0; b < 4; b++)
#pragma unroll
            for (int c = 0; c < 4; c++) acc[a][b][c] = 0.0f;

    auto load_stage = [&](int s, int kt) {
        int k0 = kt * BK;
        for (int id = threadIdx.x; id < 768; id += 256) {
            const __half* src;
            __half* dst;
            if (id < 512) {
                int r = id >> 2, col = (id & 3) * 8;
                src = g_Ah + (size_t)(m_blk + r) * DMODEL + k0 + col;
                dst = &sA[s][r][col];
            } else {
                int c = id - 512;
                int r = c >> 2, col = (c & 3) * 8;
                src = g_WhT + (size_t)(n_blk + r) * DMODEL + k0 + col;
                dst = &sW[s][r][col];
            }
            unsigned sa = (unsigned)__cvta_generic_to_shared(dst);
            asm volatile("cp.async.cg.shared.global [%0], [%1], 16;" :: "r"(sa), "l"(src));
        }
    };

    load_stage(0, 0);
    asm volatile("cp.async.commit_group;");

    for (int kt = 0; kt < KT; kt++) {
        int s = kt & 1;
        if (kt + 1 < KT) {
            load_stage(s ^ 1, kt + 1);
            asm volatile("cp.async.commit_group;");
            asm volatile("cp.async.wait_group 1;");
        } else {
            asm volatile("cp.async.wait_group 0;");
        }
        __syncthreads();

#pragma unroll
        for (int ks = 0; ks < 2; ks++) {
            const int kk = ks * 16;
            uint32_t af[2][4];
            uint32_t bf[2][4];
#pragma unroll
            for (int fm = 0; fm < 2; fm++) {
                unsigned pa = (unsigned)__cvta_generic_to_shared(
                    &sA[s][wm + fm * 16 + aRow][kk + aCol]);
                LDSM4(af[fm], pa);
            }
#pragma unroll
            for (int fb = 0; fb < 2; fb++) {
                unsigned pb = (unsigned)__cvta_generic_to_shared(
                    &sW[s][wn + fb * 16 + bRow][kk + bCol]);
                LDSM4(bf[fb], pb);
            }
#pragma unroll
            for (int fm = 0; fm < 2; fm++)
#pragma unroll
                for (int fn = 0; fn < 4; fn++) {
                    const uint32_t* B = &bf[fn >> 1][(fn & 1) * 2];
                    MMA_F16(acc[fm][fn], af[fm], B);
                }
        }
        __syncthreads();
    }

    // write pre (+bias), skip pad cols
#pragma unroll
    for (int fm = 0; fm < 2; fm++)
#pragma unroll
        for (int fn = 0; fn < 4; fn++) {
            int row = m_blk + wm + fm * 16 + g;
            int col = n_blk + wn + fn * 8 + tq * 2;
            if (col < ODIM) {
                float bb = __ldg(&b1[col]);
                g_pre[(size_t)row * ODIM + col] = acc[fm][fn][0] + bb;
                g_pre[(size_t)(row + 8) * ODIM + col] = acc[fm][fn][2] + bb;
            }
            if (col + 1 < ODIM) {
                float bb = __ldg(&b1[col + 1]);
                g_pre[(size_t)row * ODIM + col + 1] = acc[fm][fn][1] + bb;
                g_pre[(size_t)(row + 8) * ODIM + col + 1] = acc[fm][fn][3] + bb;
            }
        }

    // ---- arrival: last CTA of this m-block becomes the finisher ----
    __threadfence();
    __syncthreads();
    if (threadIdx.x == 0) {
        unsigned old = atomicAdd(&g_cnt[blockIdx.y], 1u);
        s_last = (old == NB - 1) ? 1u : 0u;
    }
    __syncthreads();
    if (!s_last) return;
    __threadfence();   // acquire: see all 9 CTAs' g_pre writes

    // ---- finisher: softmax + gumbel-argmax + gather + residual, warp per row ----
    for (int r = warp; r < BM; r += 8) {
        const int row = m_blk + r;
        const float* pre = g_pre + (size_t)row * ODIM;

        float v[18];
        float lmax = -3.4e38f;
        float bt = -3.4e38f;
        int bj = ODIM;
#pragma unroll
        for (int jj = 0; jj < 18; jj++) {
            int j = lane + jj * 32;
            if (j < ODIM) {
                float x = pre[j];
                v[jj] = x;
                lmax = fmaxf(lmax, x);
                float t = x + gumbel_at((uint32_t)(row * ODIM + j));
                if (t > bt) { bt = t; bj = j; }   // ascending j -> lowest on ties
            }
        }
#pragma unroll
        for (int o = 16; o > 0; o >>= 1) {
            lmax = fmaxf(lmax, __shfl_xor_sync(0xffffffffu, lmax, o));
            float ot = __shfl_xor_sync(0xffffffffu, bt, o);
            int oj = __shfl_xor_sync(0xffffffffu, bj, o);
            if (ot > bt || (ot == bt && oj < bj)) { bt = ot; bj = oj; }
        }

        float lsum = 0.0f;
#pragma unroll
        for (int jj = 0; jj < 18; jj++) {
            int j = lane + jj * 32;
            if (j < ODIM) {
                float e = __expf(v[jj] - lmax);
                v[jj] = e;
                lsum += e;
            }
        }
#pragma unroll
        for (int o = 16; o > 0; o >>= 1) lsum += __shfl_xor_sync(0xffffffffu, lsum, o);
        float inv = 1.0f / lsum;

        float* probs = out + (size_t)row * ODIM;
#pragma unroll
        for (int jj = 0; jj < 18; jj++) {
            int j = lane + jj * 32;
            if (j < ODIM) probs[j] = v[jj] * inv;
        }

        // gather + relu + residual (vectorized)
        const float4* w4 = (const float4*)(W2 + (size_t)bj * DMODEL);
        const float4* b4 = (const float4*)b2;
        const float4* c4 = (const float4*)(core + (size_t)row * DMODEL);
        float4* e4 = (float4*)(out + (size_t)BATCH * ODIM + (size_t)row * DMODEL);
#pragma unroll
        for (int jj = 0; jj < 8; jj++) {
            int j = lane + jj * 32;
            float4 w = __ldg(&w4[j]);
            float4 bb = b4[j];
            float4 c = c4[j];
            float4 o;
            o.x = fmaxf(w.x + bb.x, 0.0f) + c.x;
            o.y = fmaxf(w.y + bb.y, 0.0f) + c.y;
            o.z = fmaxf(w.z + bb.z, 0.0f) + c.z;
            o.w = fmaxf(w.w + bb.w, 0.0f) + c.w;
            e4[j] = o;
        }
    }

    // reset counter for next graph replay
    __syncthreads();
    if (threadIdx.x == 0) g_cnt[blockIdx.y] = 0u;
}

// ---------------- launch ----------------
extern "C" void kernel_launch(void* const* d_in, const int* in_sizes, int n_in,
                              void* d_out, int out_size) {
    const float* core = (const float*)d_in[0];
    const float* W1   = (const float*)d_in[1];
    const float* b1   = (const float*)d_in[2];
    const float* W2   = (const float*)d_in[3];
    const float* b2   = (const float*)d_in[4];
    float* out = (float*)d_out;

    convert_a_kernel<<<2048, 256>>>(core);
    convert_w_kernel<<<288, 256>>>(W1);
    gemm_kernel<<<dim3(NB, NMB), 256>>>(b1, core, W2, b2, out);
}

// round 14
// speedup vs baseline: 1.6177x; 1.6177x over previous
#include <cuda_runtime.h>
#include <cuda_fp16.h>
#include <cstdint>

#define BATCH 16384
#define DMODEL 1024
#define ODIM 572
#define ODIM_PAD 576

#define BM 128
#define BN 64
#define BK 32
#define KT (DMODEL / BK)
#define SSTRIDE 40  // 32 + 8 pad: 80B rows -> conflict-free ldmatrix, 16B-aligned

// ---------------- scratch (device globals; no allocation) ----------------
__device__ __half g_Ah[BATCH * DMODEL];              // A rounded once to fp16
__device__ __half g_WhT[ODIM_PAD * DMODEL];          // [n][k] transposed, padded, fp16
__device__ float g_pre[BATCH * ODIM];
__device__ float g_gum[BATCH * ODIM];                // precomputed gumbel noise

// ---------------- Threefry-2x32, key = PRNGKey(42) = (0, 42) ----------------
__device__ __forceinline__ uint32_t rotl32(uint32_t v, int d) {
    return __funnelshift_l(v, v, d);
}

__device__ __forceinline__ void threefry_0_42(uint32_t c0, uint32_t c1,
                                              uint32_t& o0, uint32_t& o1) {
    const uint32_t K0 = 0u, K1 = 42u, K2 = 0u ^ 42u ^ 0x1BD11BDAu;
    uint32_t x0 = c0 + K0;
    uint32_t x1 = c1 + K1;
#define RND(r) { x0 += x1; x1 = rotl32(x1, r) ^ x0; }
    RND(13) RND(15) RND(26) RND(6)
    x0 += K1; x1 += K2 + 1u;
    RND(17) RND(29) RND(16) RND(24)
    x0 += K2; x1 += K0 + 2u;
    RND(13) RND(15) RND(26) RND(6)
    x0 += K0; x1 += K1 + 3u;
    RND(17) RND(29) RND(16) RND(24)
    x0 += K1; x1 += K2 + 4u;
    RND(13) RND(15) RND(26) RND(6)
    x0 += K2; x1 += K0 + 5u;
#undef RND
    o0 = x0; o1 = x1;
}

// JAX threefry_partitionable random_bits, bit_width=32:
//   counter words (0, elem); 32-bit output = bits1 ^ bits2
__device__ __forceinline__ float gumbel_at(uint32_t elem) {
    uint32_t o0, o1;
    threefry_0_42(0u, elem, o0, o1);
    uint32_t bits = o0 ^ o1;
    const float TINY = 1.17549435e-38f;
    float f = __uint_as_float((bits >> 9) | 0x3F800000u) - 1.0f;  // [0,1)
    float u = fmaxf(TINY, f + TINY);
    return -__logf(-__logf(u));
}

// ---------------- convert A (fp32->fp16) + gumbel precompute ----------------
// DRAM-bound kernel with ~82% idle issue slots: the threefry ALU chain hides
// under the conversion's memory wall.
__global__ void convert_a_kernel(const float* __restrict__ A) {
    int stride = gridDim.x * blockDim.x;
    int tid0 = blockIdx.x * blockDim.x + threadIdx.x;
    const float2* A2 = (const float2*)A;
    __half2* out2 = (__half2*)g_Ah;
    for (int i = tid0; i < BATCH * DMODEL / 2; i += stride) {
        float2 a = A2[i];
        out2[i] = __floats2half2_rn(a.x, a.y);
    }
    for (int i = tid0; i < BATCH * ODIM; i += stride) {
        g_gum[i] = gumbel_at((uint32_t)i);
    }
}

// ---------------- convert W1: transpose + pad + fp16 ----------------
__global__ void convert_w_kernel(const float* __restrict__ W1) {
    int stride = gridDim.x * blockDim.x;
    for (int i = blockIdx.x * blockDim.x + threadIdx.x; i < ODIM_PAD * DMODEL; i += stride) {
        int n = i >> 10;          // DMODEL = 1024
        int k = i & 1023;
        float w = (n < ODIM) ? __ldg(&W1[k * ODIM + n]) : 0.0f;
        g_WhT[i] = __float2half(w);   // i == n*1024 + k
    }
}

// ---------------- GEMM: pre = core @ W1 + b1 (fp16, ldmatrix feed) ----------------
#define MMA_F16(C, A, B)                                                      \
    asm volatile(                                                             \
        "mma.sync.aligned.m16n8k16.row.col.f32.f16.f16.f32 "                  \
        "{%0,%1,%2,%3}, {%4,%5,%6,%7}, {%8,%9}, {%0,%1,%2,%3};"               \
        : "+f"(C[0]), "+f"(C[1]), "+f"(C[2]), "+f"(C[3])                      \
        : "r"((A)[0]), "r"((A)[1]), "r"((A)[2]), "r"((A)[3]),                 \
          "r"((B)[0]), "r"((B)[1]))

#define LDSM4(R, addr)                                                        \
    asm volatile("ldmatrix.sync.aligned.m8n8.x4.shared.b16 {%0,%1,%2,%3}, [%4];" \
        : "=r"((R)[0]), "=r"((R)[1]), "=r"((R)[2]), "=r"((R)[3]) : "r"(addr))

__global__ __launch_bounds__(256, 2) void gemm_kernel(const float* __restrict__ b1) {
    __shared__ __align__(16) __half sA[2][BM][SSTRIDE];     // 20480 B
    __shared__ __align__(16) __half sW[2][BN][SSTRIDE];     // 10240 B

    const int m_blk = blockIdx.y * BM;     // grid = (9, 128): n fast -> A tile reuse in wave
    const int n_blk = blockIdx.x * BN;

    const int lane = threadIdx.x & 31;
    const int warp = threadIdx.x >> 5;     // 0..7
    const int wm = (warp & 3) * 32;        // 4 warps along M
    const int wn = (warp >> 2) * 32;       // 2 warps along N
    const int g = lane >> 2;   // 0..7
    const int tq = lane & 3;   // 0..3

    const int aRow = lane & 15;
    const int aCol = (lane & 16) >> 1;
    const int bRow = (lane & 7) + ((lane & 16) >> 1);
    const int bCol = lane & 8;

    float acc[2][4][4];
#pragma unroll
    for (int a = 0; a < 2; a++)
#pragma unroll
        for (int b = 0; b < 4; b++)
#pragma unroll
            for (int c = 0; c < 4; c++) acc[a][b][c] = 0.0f;

    auto load_stage = [&](int s, int kt) {
        int k0 = kt * BK;
        for (int id = threadIdx.x; id < 768; id += 256) {
            const __half* src;
            __half* dst;
            if (id < 512) {
                int r = id >> 2, col = (id & 3) * 8;
                src = g_Ah + (size_t)(m_blk + r) * DMODEL + k0 + col;
                dst = &sA[s][r][col];
            } else {
                int c = id - 512;
                int r = c >> 2, col = (c & 3) * 8;
                src = g_WhT + (size_t)(n_blk + r) * DMODEL + k0 + col;
                dst = &sW[s][r][col];
            }
            unsigned sa = (unsigned)__cvta_generic_to_shared(dst);
            asm volatile("cp.async.cg.shared.global [%0], [%1], 16;" :: "r"(sa), "l"(src));
        }
    };

    load_stage(0, 0);
    asm volatile("cp.async.commit_group;");

    for (int kt = 0; kt < KT; kt++) {
        int s = kt & 1;
        if (kt + 1 < KT) {
            load_stage(s ^ 1, kt + 1);
            asm volatile("cp.async.commit_group;");
            asm volatile("cp.async.wait_group 1;");
        } else {
            asm volatile("cp.async.wait_group 0;");
        }
        __syncthreads();

#pragma unroll
        for (int ks = 0; ks < 2; ks++) {
            const int kk = ks * 16;
            uint32_t af[2][4];
            uint32_t bf[2][4];
#pragma unroll
            for (int fm = 0; fm < 2; fm++) {
                unsigned pa = (unsigned)__cvta_generic_to_shared(
                    &sA[s][wm + fm * 16 + aRow][kk + aCol]);
                LDSM4(af[fm], pa);
            }
#pragma unroll
            for (int fb = 0; fb < 2; fb++) {
                unsigned pb = (unsigned)__cvta_generic_to_shared(
                    &sW[s][wn + fb * 16 + bRow][kk + bCol]);
                LDSM4(bf[fb], pb);
            }
#pragma unroll
            for (int fm = 0; fm < 2; fm++)
#pragma unroll
                for (int fn = 0; fn < 4; fn++) {
                    const uint32_t* B = &bf[fn >> 1][(fn & 1) * 2];
                    MMA_F16(acc[fm][fn], af[fm], B);
                }
        }
        __syncthreads();
    }

    // epilogue: add bias, write pre (skip pad cols)
#pragma unroll
    for (int fm = 0; fm < 2; fm++)
#pragma unroll
        for (int fn = 0; fn < 4; fn++) {
            int row = m_blk + wm + fm * 16 + g;
            int col = n_blk + wn + fn * 8 + tq * 2;
            if (col < ODIM) {
                float bb = b1[col];
                g_pre[row * ODIM + col] = acc[fm][fn][0] + bb;
                g_pre[(row + 8) * ODIM + col] = acc[fm][fn][2] + bb;
            }
            if (col + 1 < ODIM) {
                float bb = b1[col + 1];
                g_pre[row * ODIM + col + 1] = acc[fm][fn][1] + bb;
                g_pre[(row + 8) * ODIM + col + 1] = acc[fm][fn][3] + bb;
            }
        }
}

// ---------------- fused softmax + categorical sample + gather + residual ----------------
__global__ __launch_bounds__(128) void epilogue_kernel(
    const float* __restrict__ core, const float* __restrict__ W2,
    const float* __restrict__ b2, float* __restrict__ out) {
    const int row = blockIdx.x;
    const int tid = threadIdx.x;
    const float* pre = g_pre + (size_t)row * ODIM;
    const float* gum = g_gum + (size_t)row * ODIM;

    __shared__ float s_max[4];
    __shared__ float s_sum[4];
    __shared__ float s_bt[4];
    __shared__ int s_bj[4];

    float v[5];
    float lmax = -3.4e38f;
    float bt = -3.4e38f;
    int bj = ODIM;

#pragma unroll
    for (int jj = 0; jj < 5; jj++) {
        int j = tid + jj * 128;
        if (j < ODIM) {
            float x = pre[j];
            v[jj] = x;
            lmax = fmaxf(lmax, x);
            float t = x + gum[j];
            if (t > bt) { bt = t; bj = j; }   // ascending j -> first max wins
        }
    }
#pragma unroll
    for (int o = 16; o > 0; o >>= 1) {
        lmax = fmaxf(lmax, __shfl_xor_sync(0xffffffffu, lmax, o));
        float ot = __shfl_xor_sync(0xffffffffu, bt, o);
        int oj = __shfl_xor_sync(0xffffffffu, bj, o);
        if (ot > bt || (ot == bt && oj < bj)) { bt = ot; bj = oj; }
    }
    if ((tid & 31) == 0) {
        s_max[tid >> 5] = lmax;
        s_bt[tid >> 5] = bt;
        s_bj[tid >> 5] = bj;
    }
    __syncthreads();
    float rmax = fmaxf(fmaxf(s_max[0], s_max[1]), fmaxf(s_max[2], s_max[3]));
    float fbt = s_bt[0]; int fbj = s_bj[0];
#pragma unroll
    for (int w = 1; w < 4; w++) {
        if (s_bt[w] > fbt || (s_bt[w] == fbt && s_bj[w] < fbj)) { fbt = s_bt[w]; fbj = s_bj[w]; }
    }

    float e[5];
    float lsum = 0.0f;
#pragma unroll
    for (int jj = 0; jj < 5; jj++) {
        int j = tid + jj * 128;
        if (j < ODIM) {
            e[jj] = __expf(v[jj] - rmax);
            lsum += e[jj];
        }
    }
#pragma unroll
    for (int o = 16; o > 0; o >>= 1) lsum += __shfl_xor_sync(0xffffffffu, lsum, o);
    if ((tid & 31) == 0) s_sum[tid >> 5] = lsum;
    __syncthreads();
    float tot = (s_sum[0] + s_sum[1]) + (s_sum[2] + s_sum[3]);
    float inv = 1.0f / tot;

    float* probs = out + (size_t)row * ODIM;
#pragma unroll
    for (int jj = 0; jj < 5; jj++) {
        int j = tid + jj * 128;
        if (j < ODIM) probs[j] = e[jj] * inv;
    }

    const int idx = fbj;
    const float* w2r = W2 + (size_t)idx * DMODEL;
    const float* cr = core + (size_t)row * DMODEL;
    float* emb = out + (size_t)BATCH * ODIM + (size_t)row * DMODEL;
#pragma unroll
    for (int jj = 0; jj < 8; jj++) {
        int j = tid + jj * 128;
        float h = __ldg(&w2r[j]) + b2[j];
        emb[j] = fmaxf(h, 0.0f) + cr[j];
    }
}

// ---------------- launch ----------------
extern "C" void kernel_launch(void* const* d_in, const int* in_sizes, int n_in,
                              void* d_out, int out_size) {
    const float* core = (const float*)d_in[0];
    const float* W1   = (const float*)d_in[1];
    const float* b1   = (const float*)d_in[2];
    const float* W2   = (const float*)d_in[3];
    const float* b2   = (const float*)d_in[4];
    float* out = (float*)d_out;

    convert_a_kernel<<<2048, 256>>>(core);
    convert_w_kernel<<<288, 256>>>(W1);
    gemm_kernel<<<dim3(ODIM_PAD / BN, BATCH / BM), 256>>>(b1);
    epilogue_kernel<<<BATCH, 128>>>(core, W2, b2, out);
}

// round 15
// speedup vs baseline: 2.0407x; 1.2615x over previous
#include <cuda_runtime.h>
#include <cuda_fp16.h>
#include <cstdint>

#define BATCH 16384
#define DMODEL 1024
#define ODIM 572
#define ODIM_PAD 576

#define BM 128
#define BN 64
#define BK 64
#define KT (DMODEL / BK)     // 16
#define SSTRIDE 72  // 64 + 8 pad: 144B rows -> conflict-free ldmatrix, 16B-aligned

// dynamic smem element offsets (half units)
#define SA_STAGE (BM * SSTRIDE)     // 9216
#define SW_STAGE (BN * SSTRIDE)     // 4608
#define OFF_SW (2 * SA_STAGE)       // 18432
#define SMEM_HALVES (2 * SA_STAGE + 2 * SW_STAGE)   // 27648 halves = 55296 B

// ---------------- scratch (device globals; no allocation) ----------------
__device__ __half g_Ah[BATCH * DMODEL];              // A rounded once to fp16
__device__ __half g_WhT[ODIM_PAD * DMODEL];          // [n][k] transposed, padded, fp16
__device__ float g_pre[BATCH * ODIM];

// ---------------- convert A: fp32 -> fp16 (vectorized) ----------------
__global__ void convert_a_kernel(const float* __restrict__ A) {
    int stride = gridDim.x * blockDim.x;
    const float2* A2 = (const float2*)A;
    __half2* out2 = (__half2*)g_Ah;
    for (int i = blockIdx.x * blockDim.x + threadIdx.x; i < BATCH * DMODEL / 2; i += stride) {
        float2 a = A2[i];
        out2[i] = __floats2half2_rn(a.x, a.y);
    }
}

// ---------------- convert W1: transpose + pad + fp16 ----------------
__global__ void convert_w_kernel(const float* __restrict__ W1) {
    int stride = gridDim.x * blockDim.x;
    for (int i = blockIdx.x * blockDim.x + threadIdx.x; i < ODIM_PAD * DMODEL; i += stride) {
        int n = i >> 10;          // DMODEL = 1024
        int k = i & 1023;
        float w = (n < ODIM) ? __ldg(&W1[k * ODIM + n]) : 0.0f;
        g_WhT[i] = __float2half(w);   // i == n*1024 + k
    }
}

// ---------------- GEMM: pre = core @ W1 + b1 (fp16, BK=64, ldmatrix feed) ----------------
#define MMA_F16(C, A, B)                                                      \
    asm volatile(                                                             \
        "mma.sync.aligned.m16n8k16.row.col.f32.f16.f16.f32 "                  \
        "{%0,%1,%2,%3}, {%4,%5,%6,%7}, {%8,%9}, {%0,%1,%2,%3};"               \
        : "+f"(C[0]), "+f"(C[1]), "+f"(C[2]), "+f"(C[3])                      \
        : "r"((A)[0]), "r"((A)[1]), "r"((A)[2]), "r"((A)[3]),                 \
          "r"((B)[0]), "r"((B)[1]))

#define LDSM4(R, addr)                                                        \
    asm volatile("ldmatrix.sync.aligned.m8n8.x4.shared.b16 {%0,%1,%2,%3}, [%4];" \
        : "=r"((R)[0]), "=r"((R)[1]), "=r"((R)[2]), "=r"((R)[3]) : "r"(addr))

__global__ __launch_bounds__(256) void gemm_kernel(const float* __restrict__ b1) {
    extern __shared__ __align__(16) __half smem[];
    __half* sA = smem;                 // [2][BM][SSTRIDE]
    __half* sW = smem + OFF_SW;        // [2][BN][SSTRIDE]

    const int m_blk = blockIdx.y * BM;     // grid = (9, 128): n fast -> A tile reuse in wave
    const int n_blk = blockIdx.x * BN;

    const int lane = threadIdx.x & 31;
    const int warp = threadIdx.x >> 5;     // 0..7
    const int wm = (warp & 3) * 32;        // 4 warps along M
    const int wn = (warp >> 2) * 32;       // 2 warps along N
    const int g = lane >> 2;   // 0..7
    const int tq = lane & 3;   // 0..3

    const int aRow = lane & 15;
    const int aCol = (lane & 16) >> 1;
    const int bRow = (lane & 7) + ((lane & 16) >> 1);
    const int bCol = lane & 8;

    float acc[2][4][4];
#pragma unroll
    for (int a = 0; a < 2; a++)
#pragma unroll
        for (int b = 0; b < 4; b++)
#pragma unroll
            for (int c = 0; c < 4; c++) acc[a][b][c] = 0.0f;

    auto load_stage = [&](int s, int kt) {
        int k0 = kt * BK;
        // 1536 16B-chunks: A 1024 (128 rows x 8), W 512 (64 rows x 8)
        for (int id = threadIdx.x; id < 1536; id += 256) {
            const __half* src;
            __half* dst;
            if (id < 1024) {
                int r = id >> 3, col = (id & 7) * 8;
                src = g_Ah + (size_t)(m_blk + r) * DMODEL + k0 + col;
                dst = sA + s * SA_STAGE + r * SSTRIDE + col;
            } else {
                int c = id - 1024;
                int r = c >> 3, col = (c & 7) * 8;
                src = g_WhT + (size_t)(n_blk + r) * DMODEL + k0 + col;
                dst = sW + s * SW_STAGE + r * SSTRIDE + col;
            }
            unsigned sa = (unsigned)__cvta_generic_to_shared(dst);
            asm volatile("cp.async.cg.shared.global [%0], [%1], 16;" :: "r"(sa), "l"(src));
        }
    };

    load_stage(0, 0);
    asm volatile("cp.async.commit_group;");

    for (int kt = 0; kt < KT; kt++) {
        int s = kt & 1;
        if (kt + 1 < KT) {
            load_stage(s ^ 1, kt + 1);
            asm volatile("cp.async.commit_group;");
            asm volatile("cp.async.wait_group 1;");
        } else {
            asm volatile("cp.async.wait_group 0;");
        }
        __syncthreads();

#pragma unroll
        for (int ks = 0; ks < 4; ks++) {
            const int kk = ks * 16;
            uint32_t af[2][4];
            uint32_t bf[2][4];
#pragma unroll
            for (int fm = 0; fm < 2; fm++) {
                unsigned pa = (unsigned)__cvta_generic_to_shared(
                    sA + s * SA_STAGE + (wm + fm * 16 + aRow) * SSTRIDE + kk + aCol);
                LDSM4(af[fm], pa);
            }
#pragma unroll
            for (int fb = 0; fb < 2; fb++) {
                unsigned pb = (unsigned)__cvta_generic_to_shared(
                    sW + s * SW_STAGE + (wn + fb * 16 + bRow) * SSTRIDE + kk + bCol);
                LDSM4(bf[fb], pb);
            }
#pragma unroll
            for (int fm = 0; fm < 2; fm++)
#pragma unroll
                for (int fn = 0; fn < 4; fn++) {
                    const uint32_t* B = &bf[fn >> 1][(fn & 1) * 2];
                    MMA_F16(acc[fm][fn], af[fm], B);
                }
        }
        __syncthreads();
    }

    // epilogue: add bias, write pre (skip pad cols)
#pragma unroll
    for (int fm = 0; fm < 2; fm++)
#pragma unroll
        for (int fn = 0; fn < 4; fn++) {
            int row = m_blk + wm + fm * 16 + g;
            int col = n_blk + wn + fn * 8 + tq * 2;
            if (col < ODIM) {
                float bb = b1[col];
                g_pre[row * ODIM + col] = acc[fm][fn][0] + bb;
                g_pre[(row + 8) * ODIM + col] = acc[fm][fn][2] + bb;
            }
            if (col + 1 < ODIM) {
                float bb = b1[col + 1];
                g_pre[row * ODIM + col + 1] = acc[fm][fn][1] + bb;
                g_pre[(row + 8) * ODIM + col + 1] = acc[fm][fn][3] + bb;
            }
        }
}

// ---------------- Threefry-2x32, key = PRNGKey(42) = (0, 42) ----------------
__device__ __forceinline__ uint32_t rotl32(uint32_t v, int d) {
    return __funnelshift_l(v, v, d);
}

__device__ __forceinline__ void threefry_0_42(uint32_t c0, uint32_t c1,
                                              uint32_t& o0, uint32_t& o1) {
    const uint32_t K0 = 0u, K1 = 42u, K2 = 0u ^ 42u ^ 0x1BD11BDAu;
    uint32_t x0 = c0 + K0;
    uint32_t x1 = c1 + K1;
#define RND(r) { x0 += x1; x1 = rotl32(x1, r) ^ x0; }
    RND(13) RND(15) RND(26) RND(6)
    x0 += K1; x1 += K2 + 1u;
    RND(17) RND(29) RND(16) RND(24)
    x0 += K2; x1 += K0 + 2u;
    RND(13) RND(15) RND(26) RND(6)
    x0 += K0; x1 += K1 + 3u;
    RND(17) RND(29) RND(16) RND(24)
    x0 += K1; x1 += K2 + 4u;
    RND(13) RND(15) RND(26) RND(6)
    x0 += K2; x1 += K0 + 5u;
#undef RND
    o0 = x0; o1 = x1;
}

// JAX threefry_partitionable random_bits, bit_width=32:
//   counter words (0, elem); 32-bit output = bits1 ^ bits2
__device__ __forceinline__ float gumbel_at(uint32_t elem) {
    uint32_t o0, o1;
    threefry_0_42(0u, elem, o0, o1);
    uint32_t bits = o0 ^ o1;
    const float TINY = 1.17549435e-38f;
    float f = __uint_as_float((bits >> 9) | 0x3F800000u) - 1.0f;  // [0,1)
    float u = fmaxf(TINY, f + TINY);
    return -__logf(-__logf(u));
}

// ---------------- fused softmax + categorical sample + gather + residual ----------------
__global__ __launch_bounds__(128) void epilogue_kernel(
    const float* __restrict__ core, const float* __restrict__ W2,
    const float* __restrict__ b2, float* __restrict__ out) {
    const int row = blockIdx.x;
    const int tid = threadIdx.x;
    const float* pre = g_pre + (size_t)row * ODIM;

    __shared__ float s_max[4];
    __shared__ float s_sum[4];
    __shared__ float s_bt[4];
    __shared__ int s_bj[4];

    float v[5];
    float lmax = -3.4e38f;
    float bt = -3.4e38f;
    int bj = ODIM;

#pragma unroll
    for (int jj = 0; jj < 5; jj++) {
        int j = tid + jj * 128;
        if (j < ODIM) {
            float x = pre[j];
            v[jj] = x;
            lmax = fmaxf(lmax, x);
            float t = x + gumbel_at((uint32_t)(row * ODIM + j));
            if (t > bt) { bt = t; bj = j; }   // ascending j -> first max wins
        }
    }
#pragma unroll
    for (int o = 16; o > 0; o >>= 1) {
        lmax = fmaxf(lmax, __shfl_xor_sync(0xffffffffu, lmax, o));
        float ot = __shfl_xor_sync(0xffffffffu, bt, o);
        int oj = __shfl_xor_sync(0xffffffffu, bj, o);
        if (ot > bt || (ot == bt && oj < bj)) { bt = ot; bj = oj; }
    }
    if ((tid & 31) == 0) {
        s_max[tid >> 5] = lmax;
        s_bt[tid >> 5] = bt;
        s_bj[tid >> 5] = bj;
    }
    __syncthreads();
    float rmax = fmaxf(fmaxf(s_max[0], s_max[1]), fmaxf(s_max[2], s_max[3]));
    float fbt = s_bt[0]; int fbj = s_bj[0];
#pragma unroll
    for (int w = 1; w < 4; w++) {
        if (s_bt[w] > fbt || (s_bt[w] == fbt && s_bj[w] < fbj)) { fbt = s_bt[w]; fbj = s_bj[w]; }
    }

    float e[5];
    float lsum = 0.0f;
#pragma unroll
    for (int jj = 0; jj < 5; jj++) {
        int j = tid + jj * 128;
        if (j < ODIM) {
            e[jj] = __expf(v[jj] - rmax);
            lsum += e[jj];
        }
    }
#pragma unroll
    for (int o = 16; o > 0; o >>= 1) lsum += __shfl_xor_sync(0xffffffffu, lsum, o);
    if ((tid & 31) == 0) s_sum[tid >> 5] = lsum;
    __syncthreads();
    float tot = (s_sum[0] + s_sum[1]) + (s_sum[2] + s_sum[3]);
    float inv = 1.0f / tot;

    float* probs = out + (size_t)row * ODIM;
#pragma unroll
    for (int jj = 0; jj < 5; jj++) {
        int j = tid + jj * 128;
        if (j < ODIM) probs[j] = e[jj] * inv;
    }

    const int idx = fbj;
    const float* w2r = W2 + (size_t)idx * DMODEL;
    const float* cr = core + (size_t)row * DMODEL;
    float* emb = out + (size_t)BATCH * ODIM + (size_t)row * DMODEL;
#pragma unroll
    for (int jj = 0; jj < 8; jj++) {
        int j = tid + jj * 128;
        float h = __ldg(&w2r[j]) + b2[j];
        emb[j] = fmaxf(h, 0.0f) + cr[j];
    }
}

// ---------------- launch ----------------
extern "C" void kernel_launch(void* const* d_in, const int* in_sizes, int n_in,
                              void* d_out, int out_size) {
    const float* core = (const float*)d_in[0];
    const float* W1   = (const float*)d_in[1];
    const float* b1   = (const float*)d_in[2];
    const float* W2   = (const float*)d_in[3];
    const float* b2   = (const float*)d_in[4];
    float* out = (float*)d_out;

    cudaFuncSetAttribute(gemm_kernel, cudaFuncAttributeMaxDynamicSharedMemorySize,
                         SMEM_HALVES * (int)sizeof(__half));

    convert_a_kernel<<<2048, 256>>>(core);
    convert_w_kernel<<<288, 256>>>(W1);
    gemm_kernel<<<dim3(ODIM_PAD / BN, BATCH / BM), 256,
                  SMEM_HALVES * sizeof(__half)>>>(b1);
    epilogue_kernel<<<BATCH, 128>>>(core, W2, b2, out);
}